// round 4
// baseline (speedup 1.0000x reference)
#include <cuda_runtime.h>
#include <math.h>

#define BS 128
#define LATENT 512
#define HID 1024
#define G4 4096   // 4*HID
#define NBLK 128
#define NTHR 256

typedef unsigned long long u64;

// Persistent device-global state (allocation-free scratch).
__device__ float g_Wx[2][G4][LATENT];   // gate-interleaved Wih per dir
__device__ float g_Wh[2][G4][HID];      // gate-interleaved Whh per dir
__device__ float g_bias[2][G4];         // gate-interleaved bias per dir
__device__ float g_x[BS][LATENT];       // current decoder input
__device__ float g_h[2][2][BS][HID];    // [buf][dir][b][j] (double-buffered)
__device__ float g_c[2][BS][HID];       // [dir][b][j]
__device__ u64   g_arrive;              // grid-barrier arrival counter

__device__ __forceinline__ u64 pack2(float lo, float hi) {
    u64 r; asm("mov.b64 %0, {%1, %2};" : "=l"(r) : "f"(lo), "f"(hi)); return r;
}
__device__ __forceinline__ void unpack2(u64 v, float& lo, float& hi) {
    asm("mov.b64 {%0, %1}, %2;" : "=f"(lo), "=f"(hi) : "l"(v));
}
__device__ __forceinline__ void fma2(u64& d, u64 a, u64 b) {
    asm("fma.rn.f32x2 %0, %1, %2, %0;" : "+l"(d) : "l"(a), "l"(b));
}

// Grid-wide barrier: monotonically increasing arrival counter (reset in prep).
// Leading threadfence = release (flush writes); trailing threadfence (gpu
// scope -> CCTL.IVALL) = acquire (invalidate stale L1 lines).
__device__ __forceinline__ void grid_sync(u64 target) {
    __threadfence();
    __syncthreads();
    if (threadIdx.x == 0) {
        atomicAdd(&g_arrive, 1ULL);
        u64 v;
        do { v = *(volatile u64*)&g_arrive; } while (v < target);
    }
    __syncthreads();
    __threadfence();
}

// ---------------------------------------------------------------------------
// Prep: gate-interleave weights (reordered row r -> orig row (r&3)*HID + (r>>2))
// so each 4-column group is a complete (i,f,g,o) quadruple. Init x, h, c, bar.
// ---------------------------------------------------------------------------
__global__ void prep_kernel(const float* __restrict__ Wih_f, const float* __restrict__ Whh_f,
                            const float* __restrict__ b_f,
                            const float* __restrict__ Wih_b, const float* __restrict__ Whh_b,
                            const float* __restrict__ b_b,
                            const float* __restrict__ dec) {
    int idx = blockIdx.x * blockDim.x + threadIdx.x;
    int stride = gridDim.x * blockDim.x;
    if (idx == 0) g_arrive = 0ULL;
    for (int i = idx; i < 2 * G4 * LATENT; i += stride) {
        int dir = i / (G4 * LATENT);
        int rem = i - dir * (G4 * LATENT);
        int r = rem / LATENT, k = rem - r * LATENT;
        int orow = (r & 3) * HID + (r >> 2);
        const float* W = dir ? Wih_b : Wih_f;
        g_Wx[dir][r][k] = W[orow * LATENT + k];
    }
    for (int i = idx; i < 2 * G4 * HID; i += stride) {
        int dir = i / (G4 * HID);
        int rem = i - dir * (G4 * HID);
        int r = rem / HID, k = rem - r * HID;
        int orow = (r & 3) * HID + (r >> 2);
        const float* W = dir ? Whh_b : Whh_f;
        g_Wh[dir][r][k] = W[orow * HID + k];
    }
    for (int i = idx; i < 2 * G4; i += stride) {
        int dir = i / G4, r = i - dir * G4;
        g_bias[dir][r] = (dir ? b_b : b_f)[(r & 3) * HID + (r >> 2)];
    }
    for (int i = idx; i < BS * LATENT; i += stride) ((float*)g_x)[i] = dec[i];
    for (int i = idx; i < 2 * BS * HID; i += stride) {
        ((float*)g_h[0])[i] = 0.f;
        ((float*)g_h[1])[i] = 0.f;
        ((float*)g_c)[i]    = 0.f;
    }
}

// ---------------------------------------------------------------------------
// Persistent kernel: all T steps in one launch. 128 blocks x 256 threads.
// Per step:
//   phase A (GEMM+cell): block = (dir, 64-col tile); M=128, N=64, K=1536.
//   grid_sync
//   phase B (head): block = (btile of 8 rows, ltile of 64 cols) for x_next;
//                   ltile==0 blocks also compute the fc1 output scalar.
//   grid_sync
// ---------------------------------------------------------------------------
__global__ void __launch_bounds__(NTHR, 1) lstm_persist(
        int T, float* __restrict__ out,
        const float* __restrict__ W_out, const float* __restrict__ b_out,
        const float* __restrict__ W_fc1, const float* __restrict__ b_fc1) {

    __shared__ __align__(16) unsigned char sraw[33 * 1024];
    u64   (*As2)[128]  = (u64 (*)[128])sraw;                 // 16 KB, dup-packed A
    float (*Bsf)[64]   = (float (*)[64])(sraw + 16384);      // 4 KB
    float (*s_hb)[HID] = (float (*)[HID])sraw;               // 32 KB (head phase)

    const int tid = threadIdx.x;
    const int bid = blockIdx.x;

    // GEMM-phase mapping
    const int dir = bid >> 6;
    const int colbase = (bid & 63) << 6;
    const int ty = tid >> 3;            // 0..31 -> rows ty*4..+3
    const int tx = tid & 7;             // 0..7  -> cols tx*8..+7
    const int ty4 = ty * 4;

    // Head-phase mapping
    const int bt = bid >> 3;            // 0..15 -> rows bt*8..+7
    const int lt = bid & 7;             // 0..7  -> latent cols lt*64..+63

    u64 nbar = 0;

    for (int t = 0; t < T; t++) {
        const int cur = t & 1;
        const int nxt = cur ^ 1;

        // ================= phase A: z-GEMM + LSTM cell =================
        u64 acc[4][4];
#pragma unroll
        for (int i = 0; i < 4; i++)
#pragma unroll
            for (int j = 0; j < 4; j++) acc[i][j] = 0ull;

#pragma unroll 1
        for (int phase = 0; phase < 2; phase++) {
            const int K = phase ? HID : LATENT;
            const float* __restrict__ A = phase ? &g_h[cur][dir][0][0] : &g_x[0][0];
            const float* __restrict__ W = phase ? &g_Wh[dir][colbase][0]
                                                : &g_Wx[dir][colbase][0];
#pragma unroll 1
            for (int k0 = 0; k0 < K; k0 += 16) {
                // stage A: 128 rows x 16 k, duplicated pairs
                {
                    int row = tid & 127;
                    int kh  = (tid >> 7) * 8;
                    const float4* ap = (const float4*)(A + row * K + k0 + kh);
                    float4 v0 = ap[0], v1 = ap[1];
                    As2[kh + 0][row] = pack2(v0.x, v0.x);
                    As2[kh + 1][row] = pack2(v0.y, v0.y);
                    As2[kh + 2][row] = pack2(v0.z, v0.z);
                    As2[kh + 3][row] = pack2(v0.w, v0.w);
                    As2[kh + 4][row] = pack2(v1.x, v1.x);
                    As2[kh + 5][row] = pack2(v1.y, v1.y);
                    As2[kh + 6][row] = pack2(v1.z, v1.z);
                    As2[kh + 7][row] = pack2(v1.w, v1.w);
                }
                // stage B: 64 cols x 16 k
                {
                    int col = tid >> 2;
                    int kq  = (tid & 3) * 4;
                    const float4* wp = (const float4*)(W + col * K + k0 + kq);
                    float4 w = wp[0];
                    Bsf[kq + 0][col] = w.x;
                    Bsf[kq + 1][col] = w.y;
                    Bsf[kq + 2][col] = w.z;
                    Bsf[kq + 3][col] = w.w;
                }
                __syncthreads();

#pragma unroll
                for (int kk = 0; kk < 16; kk++) {
                    ulonglong2 a01 = *(const ulonglong2*)&As2[kk][ty4];
                    ulonglong2 a23 = *(const ulonglong2*)&As2[kk][ty4 + 2];
                    const ulonglong2* bp = (const ulonglong2*)&Bsf[kk][tx * 8];
                    ulonglong2 b01 = bp[0], b23 = bp[1];
                    fma2(acc[0][0], a01.x, b01.x); fma2(acc[0][1], a01.x, b01.y);
                    fma2(acc[0][2], a01.x, b23.x); fma2(acc[0][3], a01.x, b23.y);
                    fma2(acc[1][0], a01.y, b01.x); fma2(acc[1][1], a01.y, b01.y);
                    fma2(acc[1][2], a01.y, b23.x); fma2(acc[1][3], a01.y, b23.y);
                    fma2(acc[2][0], a23.x, b01.x); fma2(acc[2][1], a23.x, b01.y);
                    fma2(acc[2][2], a23.x, b23.x); fma2(acc[2][3], a23.x, b23.y);
                    fma2(acc[3][0], a23.y, b01.x); fma2(acc[3][1], a23.y, b01.y);
                    fma2(acc[3][2], a23.y, b23.x); fma2(acc[3][3], a23.y, b23.y);
                }
                __syncthreads();
            }
        }

        // cell epilogue: 2 (i,f,g,o) quadruples x 4 rows per thread
#pragma unroll
        for (int grp = 0; grp < 2; grp++) {
            const int cb = colbase + tx * 8 + grp * 4;
            const int jprime = cb >> 2;
            const float bi = g_bias[dir][cb + 0];
            const float bf = g_bias[dir][cb + 1];
            const float bg = g_bias[dir][cb + 2];
            const float bo = g_bias[dir][cb + 3];
#pragma unroll
            for (int i = 0; i < 4; i++) {
                const int row = ty4 + i;
                float zi, zf, zg, zo;
                unpack2(acc[i][grp * 2 + 0], zi, zf);
                unpack2(acc[i][grp * 2 + 1], zg, zo);
                zi += bi; zf += bf; zg += bg; zo += bo;
                float si = 1.f / (1.f + expf(-zi));
                float sf = 1.f / (1.f + expf(-zf));
                float so = 1.f / (1.f + expf(-zo));
                float c2 = sf * g_c[dir][row][jprime] + si * tanhf(zg);
                g_c[dir][row][jprime] = c2;
                g_h[nxt][dir][row][jprime] = so * tanhf(c2);
            }
        }

        nbar++; grid_sync(nbar * NBLK);

        // ================= phase B: head =================
        // stage hb rows bt*8..+7 into smem
        for (int i = tid; i < 8 * HID / 4; i += NTHR) {
            int r = (i * 4) >> 10;
            int k = (i * 4) & (HID - 1);
            *(float4*)&s_hb[r][k] = *(const float4*)&g_h[nxt][1][bt * 8 + r][k];
        }
        __syncthreads();

        // x_next = hb @ W_out^T + b_out  (this block: 8 b-rows x 64 l-cols)
        {
            const int l_loc = tid >> 2;
            const int q = tid & 3;
            const int l = lt * 64 + l_loc;
            const u64* __restrict__ wp = (const u64*)(W_out + (size_t)l * HID + q * 256);
            const u64* __restrict__ hp = (const u64*)&s_hb[0][q * 256];
            u64 hacc[8];
#pragma unroll
            for (int r = 0; r < 8; r++) hacc[r] = 0ull;
#pragma unroll 2
            for (int k2 = 0; k2 < 128; k2++) {
                u64 w = wp[k2];
#pragma unroll
                for (int r = 0; r < 8; r++) fma2(hacc[r], w, hp[r * 512 + k2]);
            }
#pragma unroll
            for (int r = 0; r < 8; r++) {
                float lo, hi; unpack2(hacc[r], lo, hi);
                float s = lo + hi;
                s += __shfl_xor_sync(0xffffffffu, s, 1);
                s += __shfl_xor_sync(0xffffffffu, s, 2);
                if (q == 0) g_x[bt * 8 + r][l] = s + b_out[l];
            }
        }

        // out[b, t] = relu(concat(hf,hb)) . W_fc1 + b_fc1  (ltile 0 blocks)
        if (lt == 0) {
            const int r = tid >> 5, lane = tid & 31;
            const int b = bt * 8 + r;
            const float* __restrict__ hf = &g_h[nxt][0][b][0];
            float facc = 0.f;
            for (int k = lane * 4; k < HID; k += 128) {
                float4 f  = *(const float4*)&hf[k];
                float4 wf = *(const float4*)&W_fc1[k];
                float4 hb4 = *(const float4*)&s_hb[r][k];
                float4 wb = *(const float4*)&W_fc1[HID + k];
                facc += fmaxf(f.x, 0.f) * wf.x + fmaxf(f.y, 0.f) * wf.y
                      + fmaxf(f.z, 0.f) * wf.z + fmaxf(f.w, 0.f) * wf.w
                      + fmaxf(hb4.x, 0.f) * wb.x + fmaxf(hb4.y, 0.f) * wb.y
                      + fmaxf(hb4.z, 0.f) * wb.z + fmaxf(hb4.w, 0.f) * wb.w;
            }
#pragma unroll
            for (int off = 16; off; off >>= 1)
                facc += __shfl_xor_sync(0xffffffffu, facc, off);
            if (lane == 0) out[(size_t)b * T + t] = facc + b_fc1[0];
        }

        nbar++; grid_sync(nbar * NBLK);
    }
}

// ---------------------------------------------------------------------------
extern "C" void kernel_launch(void* const* d_in, const int* in_sizes, int n_in,
                              void* d_out, int out_size) {
    const float* dec   = (const float*)d_in[0];
    // d_in[1] = lengths (T derives from out_size)
    const float* Wih_f = (const float*)d_in[2];
    const float* Whh_f = (const float*)d_in[3];
    const float* b_f   = (const float*)d_in[4];
    const float* Wih_b = (const float*)d_in[5];
    const float* Whh_b = (const float*)d_in[6];
    const float* b_b   = (const float*)d_in[7];
    const float* W_out = (const float*)d_in[8];
    const float* b_out = (const float*)d_in[9];
    const float* W_fc1 = (const float*)d_in[10];
    const float* b_fc1 = (const float*)d_in[11];
    float* out = (float*)d_out;

    const int T = out_size / BS;

    prep_kernel<<<1024, 256>>>(Wih_f, Whh_f, b_f, Wih_b, Whh_b, b_b, dec);
    if (T > 0) {
        lstm_persist<<<NBLK, NTHR>>>(T, out, W_out, b_out, W_fc1, b_fc1);
    }
}

// round 6
// speedup vs baseline: 2.4370x; 2.4370x over previous
#include <cuda_runtime.h>
#include <cuda_bf16.h>
#include <math.h>
#include <stdint.h>

#define BS 128
#define LATENT 512
#define HID 1024
#define G4 4096       // 4*HID
#define KTOT 1536     // LATENT + HID unified K
#define NBLK 128
#define NTHR 256
#define NCHUNK 24     // KTOT / 64
#define CHK 64        // bf16 K elems per chunk (= 128 bytes/row)

typedef unsigned long long u64;
typedef unsigned int u32;

// ---------------- persistent device-global state (no runtime alloc) --------
__device__ __align__(16) __nv_bfloat16 g_Whi[2][G4][KTOT];    // weight hi, gate-interleaved
__device__ __align__(16) __nv_bfloat16 g_Wlo[2][G4][KTOT];    // weight lo
__device__ __align__(16) __nv_bfloat16 g_Ahi[2][2][BS][KTOT]; // [buf][dir][row][k] activation hi
__device__ __align__(16) __nv_bfloat16 g_Alo[2][2][BS][KTOT]; // activation lo
__device__ __align__(16) float g_bias[2][G4];                 // gate-interleaved bias
__device__ __align__(16) float g_h[2][2][BS][HID];            // fp32 h for head [buf][dir]
__device__ __align__(16) float g_c[2][BS][HID];               // cell state [dir]
__device__ u64 g_arrive;                                      // grid barrier counter

// ---------------- helpers --------------------------------------------------
__device__ __forceinline__ void unpack2(u64 v, float& lo, float& hi) {
    asm("mov.b64 {%0, %1}, %2;" : "=f"(lo), "=f"(hi) : "l"(v));
}
__device__ __forceinline__ void fma2(u64& d, u64 a, u64 b) {
    asm("fma.rn.f32x2 %0, %1, %2, %0;" : "+l"(d) : "l"(a), "l"(b));
}
__device__ __forceinline__ u32 smem_u32(const void* p) {
    u32 a; asm("{ .reg .u64 t; cvta.to.shared.u64 t, %1; cvt.u32.u64 %0, t; }" : "=r"(a) : "l"(p));
    return a;
}

#define SW128(x) ((x) ^ (((x) >> 3) & 0x70))

#define LDSM4(R, A)                                                          \
    asm volatile("ldmatrix.sync.aligned.m8n8.x4.shared.b16 {%0,%1,%2,%3}, [%4];" \
                 : "=r"((R)[0]), "=r"((R)[1]), "=r"((R)[2]), "=r"((R)[3])    \
                 : "r"(A))

#define MMA16816(D, A, B0, B1)                                               \
    asm volatile("mma.sync.aligned.m16n8k16.row.col.f32.bf16.bf16.f32 "      \
                 "{%0,%1,%2,%3}, {%4,%5,%6,%7}, {%8,%9}, {%0,%1,%2,%3};"     \
                 : "+f"((D)[0]), "+f"((D)[1]), "+f"((D)[2]), "+f"((D)[3])    \
                 : "r"((A)[0]), "r"((A)[1]), "r"((A)[2]), "r"((A)[3]),       \
                   "r"(B0), "r"(B1))

// grid-wide barrier (release via threadfence; acquire via trailing gpu-scope
// threadfence -> CCTL.IVALL invalidates stale L1 lines)
__device__ __forceinline__ void grid_sync(u64 target) {
    __threadfence();
    __syncthreads();
    if (threadIdx.x == 0) {
        atomicAdd(&g_arrive, 1ULL);
        u64 v;
        do { v = *(volatile u64*)&g_arrive; } while (v < target);
    }
    __syncthreads();
    __threadfence();
}

// smem layout (static 48 KB): Ah 16K | Al 16K | Wh 8K | Wl 8K
#define OFF_AL 16384
#define OFF_WH 32768
#define OFF_WL 40960

// ---------------------------------------------------------------------------
// prep: gate-interleave + bf16-split weights into unified-K layout; init
// activations buf0 (x part = decoder_input, h part = 0), h, c, barrier.
// reordered row r -> orig row (r&3)*HID + (r>>2); K: [0,512)=Wih, [512,1536)=Whh
// ---------------------------------------------------------------------------
__global__ void prep_kernel(const float* __restrict__ Wih_f, const float* __restrict__ Whh_f,
                            const float* __restrict__ b_f,
                            const float* __restrict__ Wih_b, const float* __restrict__ Whh_b,
                            const float* __restrict__ b_b,
                            const float* __restrict__ dec) {
    int idx = blockIdx.x * blockDim.x + threadIdx.x;
    int stride = gridDim.x * blockDim.x;
    if (idx == 0) g_arrive = 0ULL;

    for (int i = idx; i < 2 * G4 * KTOT; i += stride) {
        int dir = i / (G4 * KTOT);
        int rem = i - dir * (G4 * KTOT);
        int r = rem / KTOT, k = rem - r * KTOT;
        int orow = (r & 3) * HID + (r >> 2);
        float w;
        if (k < LATENT) w = (dir ? Wih_b : Wih_f)[orow * LATENT + k];
        else            w = (dir ? Whh_b : Whh_f)[orow * HID + (k - LATENT)];
        __nv_bfloat16 hi = __float2bfloat16_rn(w);
        __nv_bfloat16 lo = __float2bfloat16_rn(w - __bfloat162float(hi));
        g_Whi[dir][r][k] = hi;
        g_Wlo[dir][r][k] = lo;
    }
    for (int i = idx; i < 2 * G4; i += stride) {
        int dir = i / G4, r = i - dir * G4;
        g_bias[dir][r] = (dir ? b_b : b_f)[(r & 3) * HID + (r >> 2)];
    }
    for (int i = idx; i < 2 * 2 * BS * KTOT; i += stride) {
        int buf = i / (2 * BS * KTOT);
        int rem = i - buf * (2 * BS * KTOT);
        int dir = rem / (BS * KTOT);
        int rem2 = rem - dir * (BS * KTOT);
        int row = rem2 / KTOT, k = rem2 - row * KTOT;
        float v = (buf == 0 && k < LATENT) ? dec[row * LATENT + k] : 0.f;
        __nv_bfloat16 hi = __float2bfloat16_rn(v);
        __nv_bfloat16 lo = __float2bfloat16_rn(v - __bfloat162float(hi));
        g_Ahi[buf][dir][row][k] = hi;
        g_Alo[buf][dir][row][k] = lo;
    }
    for (int i = idx; i < 2 * 2 * BS * HID; i += stride) ((float*)g_h)[i] = 0.f;
    for (int i = idx; i < 2 * BS * HID; i += stride)     ((float*)g_c)[i] = 0.f;
}

// ---------------------------------------------------------------------------
// persistent kernel: 128 blocks x 256 threads, one launch for all T steps.
// phase A: block = (dir, 64 gate-cols). z via bf16 3-split mma.sync HMMA,
//          fp32 accum in registers, LSTM cell in epilogue.
// phase B: head (x_next GEMM + fc1), FFMA2.
// ---------------------------------------------------------------------------
__global__ void __launch_bounds__(NTHR, 1) lstm_persist(
        int T, float* __restrict__ out,
        const float* __restrict__ W_out, const float* __restrict__ b_out,
        const float* __restrict__ W_fc1, const float* __restrict__ b_fc1) {

    __shared__ __align__(16) unsigned char sraw[49152];
    const u32 smem_base = smem_u32(sraw);

    const int tid = threadIdx.x;
    const int bid = blockIdx.x;
    const int wid = tid >> 5;
    const int lane = tid & 31;

    const int dir = bid >> 6;
    const int colbase = (bid & 63) << 6;

    // warp tile mapping: 4 warps along M (32 rows), 2 along N (32 cols)
    const int wm = wid & 3;
    const int wn = wid >> 2;
    const int R0 = wm * 32;
    const int C0 = wn * 32;

    // ldmatrix per-lane constants
    const int arow = lane & 15;                       // A: m16 row within tile
    const u32 khA = (u32)(lane >> 4) * 16;            // A: k-half byte offset
    const int brow = (lane & 7) + ((lane >> 4) & 1) * 8; // B: n row within n16 pair
    const u32 khB = (u32)((lane >> 3) & 1) * 16;      // B: k-half byte offset
    const u32 swA = (u32)(arow & 7) << 4;
    const u32 swB = (u32)(brow & 7) << 4;
    u32 aoff[2], boff[2];
#pragma unroll
    for (int mt = 0; mt < 2; mt++) aoff[mt] = smem_base + (u32)(R0 + mt * 16 + arow) * 128;
#pragma unroll
    for (int np = 0; np < 2; np++) boff[np] = smem_base + OFF_WH + (u32)(C0 + np * 16 + brow) * 128;

    // head mapping
    const int bt = bid >> 3;   // 16 row-tiles of 8
    const int lt = bid & 7;    // 8 latent col-tiles of 64
    float (*s_hb)[HID] = (float (*)[HID])sraw;

    u64 nbar = 0;

    for (int t = 0; t < T; t++) {
        const int cur = t & 1;
        const int nxt = cur ^ 1;

        // ================= phase A: bf16-split HMMA over 24 chunks =========
        float acc[2][4][4];
#pragma unroll
        for (int mt = 0; mt < 2; mt++)
#pragma unroll
            for (int nt = 0; nt < 4; nt++)
#pragma unroll
                for (int i = 0; i < 4; i++) acc[mt][nt][i] = 0.f;

        // prefetch chunk 0 into registers
        uint4 ra[4], rl[4], rwh[2], rwl[2];
#pragma unroll
        for (int i = 0; i < 4; i++) {
            int p = tid + i * NTHR, row = p >> 3, q = p & 7;
            ra[i] = *(const uint4*)((const char*)&g_Ahi[cur][dir][row][0] + q * 16);
            rl[i] = *(const uint4*)((const char*)&g_Alo[cur][dir][row][0] + q * 16);
        }
#pragma unroll
        for (int i = 0; i < 2; i++) {
            int p = tid + i * NTHR, row = p >> 3, q = p & 7;
            rwh[i] = *(const uint4*)((const char*)&g_Whi[dir][colbase + row][0] + q * 16);
            rwl[i] = *(const uint4*)((const char*)&g_Wlo[dir][colbase + row][0] + q * 16);
        }

#pragma unroll 1
        for (int c = 0; c < NCHUNK; c++) {
            __syncthreads();   // all warps done reading smem (prev chunk / prev-step head)
#pragma unroll
            for (int i = 0; i < 4; i++) {
                int p = tid + i * NTHR, row = p >> 3, q = p & 7;
                u32 off = SW128((u32)(row * 128 + q * 16));
                *(uint4*)(sraw + off) = ra[i];
                *(uint4*)(sraw + OFF_AL + off) = rl[i];
            }
#pragma unroll
            for (int i = 0; i < 2; i++) {
                int p = tid + i * NTHR, row = p >> 3, q = p & 7;
                u32 off = SW128((u32)(row * 128 + q * 16));
                *(uint4*)(sraw + OFF_WH + off) = rwh[i];
                *(uint4*)(sraw + OFF_WL + off) = rwl[i];
            }
            __syncthreads();

            // prefetch next chunk (overlaps MMA below)
            if (c + 1 < NCHUNK) {
                const int c64 = (c + 1) * CHK;
#pragma unroll
                for (int i = 0; i < 4; i++) {
                    int p = tid + i * NTHR, row = p >> 3, q = p & 7;
                    ra[i] = *(const uint4*)((const char*)&g_Ahi[cur][dir][row][c64] + q * 16);
                    rl[i] = *(const uint4*)((const char*)&g_Alo[cur][dir][row][c64] + q * 16);
                }
#pragma unroll
                for (int i = 0; i < 2; i++) {
                    int p = tid + i * NTHR, row = p >> 3, q = p & 7;
                    rwh[i] = *(const uint4*)((const char*)&g_Whi[dir][colbase + row][c64] + q * 16);
                    rwl[i] = *(const uint4*)((const char*)&g_Wlo[dir][colbase + row][c64] + q * 16);
                }
            }

            // consume: 4 k16 slices, 3-split
#pragma unroll
            for (int kk = 0; kk < 4; kk++) {
                const u32 xA = ((u32)(kk * 32) + khA) ^ swA;
                const u32 xB = ((u32)(kk * 32) + khB) ^ swB;
                u32 ah[2][4], al[2][4], bh[2][4], bl[2][4];
#pragma unroll
                for (int mt = 0; mt < 2; mt++) {
                    LDSM4(ah[mt], aoff[mt] + xA);
                    LDSM4(al[mt], aoff[mt] + OFF_AL + xA);
                }
#pragma unroll
                for (int np = 0; np < 2; np++) {
                    LDSM4(bh[np], boff[np] + xB);
                    LDSM4(bl[np], boff[np] + (OFF_WL - OFF_WH) + xB);
                }
#pragma unroll
                for (int mt = 0; mt < 2; mt++)
#pragma unroll
                    for (int np = 0; np < 2; np++)
#pragma unroll
                        for (int hf = 0; hf < 2; hf++) {
                            const int nt = np * 2 + hf;
                            MMA16816(acc[mt][nt], ah[mt], bh[np][2 * hf], bh[np][2 * hf + 1]);
                            MMA16816(acc[mt][nt], ah[mt], bl[np][2 * hf], bl[np][2 * hf + 1]);
                            MMA16816(acc[mt][nt], al[mt], bh[np][2 * hf], bh[np][2 * hf + 1]);
                        }
            }
        }

        // -------- epilogue: pair-exchange quads, LSTM cell, write h --------
#pragma unroll
        for (int mt = 0; mt < 2; mt++)
#pragma unroll
            for (int nt = 0; nt < 4; nt++) {
                float d0 = acc[mt][nt][0], d1 = acc[mt][nt][1];
                float d2 = acc[mt][nt][2], d3 = acc[mt][nt][3];
                float p0 = __shfl_xor_sync(0xffffffffu, d0, 1);
                float p1 = __shfl_xor_sync(0xffffffffu, d1, 1);
                float p2 = __shfl_xor_sync(0xffffffffu, d2, 1);
                float p3 = __shfl_xor_sync(0xffffffffu, d3, 1);
                if (!(lane & 1)) {
                    const int q = (lane >> 1) & 1;
                    const int col4 = colbase + C0 + nt * 8 + q * 4;
                    const int jp = col4 >> 2;
                    const float4 b4 = *(const float4*)&g_bias[dir][col4];
                    const int r0 = R0 + mt * 16 + (lane >> 2);
#pragma unroll
                    for (int rr = 0; rr < 2; rr++) {
                        const int row = r0 + rr * 8;
                        float zi = (rr ? d2 : d0) + b4.x;
                        float zf = (rr ? d3 : d1) + b4.y;
                        float zg = (rr ? p2 : p0) + b4.z;
                        float zo = (rr ? p3 : p1) + b4.w;
                        float si = 1.f / (1.f + expf(-zi));
                        float sf = 1.f / (1.f + expf(-zf));
                        float so = 1.f / (1.f + expf(-zo));
                        float c2 = sf * g_c[dir][row][jp] + si * tanhf(zg);
                        g_c[dir][row][jp] = c2;
                        float hv = so * tanhf(c2);
                        g_h[nxt][dir][row][jp] = hv;
                        __nv_bfloat16 hhi = __float2bfloat16_rn(hv);
                        __nv_bfloat16 hlo = __float2bfloat16_rn(hv - __bfloat162float(hhi));
                        g_Ahi[nxt][dir][row][LATENT + jp] = hhi;
                        g_Alo[nxt][dir][row][LATENT + jp] = hlo;
                    }
                }
            }

        nbar++; grid_sync(nbar * NBLK);

        // ================= phase B: head ===================================
        for (int i = tid; i < 8 * HID / 4; i += NTHR) {
            int r = (i * 4) >> 10;
            int k = (i * 4) & (HID - 1);
            *(float4*)&s_hb[r][k] = *(const float4*)&g_h[nxt][1][bt * 8 + r][k];
        }
        __syncthreads();

        // x_next = hb @ W_out^T + b_out, split to bf16 hi/lo for both dirs
        {
            const int l_loc = tid >> 2;
            const int q = tid & 3;
            const int l = lt * 64 + l_loc;
            const u64* __restrict__ wp = (const u64*)(W_out + (size_t)l * HID + q * 256);
            const u64* __restrict__ hp = (const u64*)&s_hb[0][q * 256];
            u64 hacc[8];
#pragma unroll
            for (int r = 0; r < 8; r++) hacc[r] = 0ull;
#pragma unroll 2
            for (int k2 = 0; k2 < 128; k2++) {
                u64 w = wp[k2];
#pragma unroll
                for (int r = 0; r < 8; r++) fma2(hacc[r], w, hp[r * 512 + k2]);
            }
#pragma unroll
            for (int r = 0; r < 8; r++) {
                float lo, hi; unpack2(hacc[r], lo, hi);
                float s = lo + hi;
                s += __shfl_xor_sync(0xffffffffu, s, 1);
                s += __shfl_xor_sync(0xffffffffu, s, 2);
                if (q == 0) {
                    float xv = s + b_out[l];
                    int row = bt * 8 + r;
                    __nv_bfloat16 xh = __float2bfloat16_rn(xv);
                    __nv_bfloat16 xl = __float2bfloat16_rn(xv - __bfloat162float(xh));
                    g_Ahi[nxt][0][row][l] = xh;
                    g_Ahi[nxt][1][row][l] = xh;
                    g_Alo[nxt][0][row][l] = xl;
                    g_Alo[nxt][1][row][l] = xl;
                }
            }
        }

        // out[b, t] = relu(concat(hf,hb)) . W_fc1 + b_fc1   (lt==0 blocks)
        if (lt == 0) {
            const int r = tid >> 5, ln = tid & 31;
            const int b = bt * 8 + r;
            const float* __restrict__ hf = &g_h[nxt][0][b][0];
            float facc = 0.f;
            for (int k = ln * 4; k < HID; k += 128) {
                float4 f   = *(const float4*)&hf[k];
                float4 wf  = *(const float4*)&W_fc1[k];
                float4 hb4 = *(const float4*)&s_hb[r][k];
                float4 wb  = *(const float4*)&W_fc1[HID + k];
                facc += fmaxf(f.x, 0.f) * wf.x + fmaxf(f.y, 0.f) * wf.y
                      + fmaxf(f.z, 0.f) * wf.z + fmaxf(f.w, 0.f) * wf.w
                      + fmaxf(hb4.x, 0.f) * wb.x + fmaxf(hb4.y, 0.f) * wb.y
                      + fmaxf(hb4.z, 0.f) * wb.z + fmaxf(hb4.w, 0.f) * wb.w;
            }
#pragma unroll
            for (int off = 16; off; off >>= 1)
                facc += __shfl_xor_sync(0xffffffffu, facc, off);
            if (ln == 0) out[(size_t)b * T + t] = facc + b_fc1[0];
        }

        nbar++; grid_sync(nbar * NBLK);
    }
}

// ---------------------------------------------------------------------------
extern "C" void kernel_launch(void* const* d_in, const int* in_sizes, int n_in,
                              void* d_out, int out_size) {
    const float* dec   = (const float*)d_in[0];
    // d_in[1] = lengths (T derives from out_size)
    const float* Wih_f = (const float*)d_in[2];
    const float* Whh_f = (const float*)d_in[3];
    const float* b_f   = (const float*)d_in[4];
    const float* Wih_b = (const float*)d_in[5];
    const float* Whh_b = (const float*)d_in[6];
    const float* b_b   = (const float*)d_in[7];
    const float* W_out = (const float*)d_in[8];
    const float* b_out = (const float*)d_in[9];
    const float* W_fc1 = (const float*)d_in[10];
    const float* b_fc1 = (const float*)d_in[11];
    float* out = (float*)d_out;

    const int T = out_size / BS;

    prep_kernel<<<1024, 256>>>(Wih_f, Whh_f, b_f, Wih_b, Whh_b, b_b, dec);
    if (T > 0) {
        lstm_persist<<<NBLK, NTHR>>>(T, out, W_out, b_out, W_fc1, b_fc1);
    }
}

// round 7
// speedup vs baseline: 2.6950x; 1.1059x over previous
#include <cuda_runtime.h>
#include <cuda_bf16.h>
#include <math.h>
#include <stdint.h>

#define BS 128
#define LATENT 512
#define HID 1024
#define G4 4096       // 4*HID
#define KTOT 1536     // LATENT + HID unified K
#define NBLK 128
#define NTHR 256
#define NCHUNK 24     // KTOT / 64
#define CHK 64        // bf16 K elems per chunk (= 128 bytes/row)

typedef unsigned long long u64;
typedef unsigned int u32;

// ---------------- persistent device-global state (no runtime alloc) --------
__device__ __align__(16) __nv_bfloat16 g_Whi[2][G4][KTOT];    // weight hi, gate-interleaved
__device__ __align__(16) __nv_bfloat16 g_Wlo[2][G4][KTOT];    // weight lo
__device__ __align__(16) __nv_bfloat16 g_Ahi[2][2][BS][KTOT]; // [buf][dir][row][k] activation hi
__device__ __align__(16) __nv_bfloat16 g_Alo[2][2][BS][KTOT]; // activation lo
__device__ __align__(16) float g_bias[2][G4];                 // gate-interleaved bias
__device__ __align__(16) float g_h[2][2][BS][HID];            // fp32 h for head [buf][dir]
__device__ __align__(16) float g_c[2][BS][HID];               // cell state [dir]
__device__ u64 g_arrive;                                      // grid barrier counter

// ---------------- helpers --------------------------------------------------
__device__ __forceinline__ void unpack2(u64 v, float& lo, float& hi) {
    asm("mov.b64 {%0, %1}, %2;" : "=f"(lo), "=f"(hi) : "l"(v));
}
__device__ __forceinline__ void fma2(u64& d, u64 a, u64 b) {
    asm("fma.rn.f32x2 %0, %1, %2, %0;" : "+l"(d) : "l"(a), "l"(b));
}
__device__ __forceinline__ u32 smem_u32(const void* p) {
    u32 a; asm("{ .reg .u64 t; cvta.to.shared.u64 t, %1; cvt.u32.u64 %0, t; }" : "=r"(a) : "l"(p));
    return a;
}

#define SW128(x) ((x) ^ (((x) >> 3) & 0x70))

#define CP16(dst, src) \
    asm volatile("cp.async.cg.shared.global [%0], [%1], 16;" :: "r"(dst), "l"(src))
#define CP_COMMIT() asm volatile("cp.async.commit_group;" ::: "memory")
#define CP_WAIT(n)  asm volatile("cp.async.wait_group %0;" :: "n"(n) : "memory")

#define LDSM4(R, A)                                                          \
    asm volatile("ldmatrix.sync.aligned.m8n8.x4.shared.b16 {%0,%1,%2,%3}, [%4];" \
                 : "=r"((R)[0]), "=r"((R)[1]), "=r"((R)[2]), "=r"((R)[3])    \
                 : "r"(A))

#define MMA16816(D, A, B0, B1)                                               \
    asm volatile("mma.sync.aligned.m16n8k16.row.col.f32.bf16.bf16.f32 "      \
                 "{%0,%1,%2,%3}, {%4,%5,%6,%7}, {%8,%9}, {%0,%1,%2,%3};"     \
                 : "+f"((D)[0]), "+f"((D)[1]), "+f"((D)[2]), "+f"((D)[3])    \
                 : "r"((A)[0]), "r"((A)[1]), "r"((A)[2]), "r"((A)[3]),       \
                   "r"(B0), "r"(B1))

// grid-wide barrier (release via threadfence; acquire via trailing gpu-scope
// threadfence -> CCTL.IVALL invalidates stale L1 lines)
__device__ __forceinline__ void grid_sync(u64 target) {
    __threadfence();
    __syncthreads();
    if (threadIdx.x == 0) {
        atomicAdd(&g_arrive, 1ULL);
        u64 v;
        do { v = *(volatile u64*)&g_arrive; } while (v < target);
    }
    __syncthreads();
    __threadfence();
}

// smem: 3 stages of 48 KB. Stage layout: Ah 16K | Al 16K | Wh 8K | Wl 8K
#define STG    49152
#define OFF_AL 16384
#define OFF_WH 32768
#define OFF_WL 40960
#define DYN_SMEM (3 * STG)

// ---------------------------------------------------------------------------
// prep: gate-interleave + bf16-split weights into unified-K layout; init
// activations buf0 (x part = decoder_input, h part = 0), h, c, barrier.
// reordered row r -> orig row (r&3)*HID + (r>>2); K: [0,512)=Wih, [512,1536)=Whh
// ---------------------------------------------------------------------------
__global__ void prep_kernel(const float* __restrict__ Wih_f, const float* __restrict__ Whh_f,
                            const float* __restrict__ b_f,
                            const float* __restrict__ Wih_b, const float* __restrict__ Whh_b,
                            const float* __restrict__ b_b,
                            const float* __restrict__ dec) {
    int idx = blockIdx.x * blockDim.x + threadIdx.x;
    int stride = gridDim.x * blockDim.x;
    if (idx == 0) g_arrive = 0ULL;

    for (int i = idx; i < 2 * G4 * KTOT; i += stride) {
        int dir = i / (G4 * KTOT);
        int rem = i - dir * (G4 * KTOT);
        int r = rem / KTOT, k = rem - r * KTOT;
        int orow = (r & 3) * HID + (r >> 2);
        float w;
        if (k < LATENT) w = (dir ? Wih_b : Wih_f)[orow * LATENT + k];
        else            w = (dir ? Whh_b : Whh_f)[orow * HID + (k - LATENT)];
        __nv_bfloat16 hi = __float2bfloat16_rn(w);
        __nv_bfloat16 lo = __float2bfloat16_rn(w - __bfloat162float(hi));
        g_Whi[dir][r][k] = hi;
        g_Wlo[dir][r][k] = lo;
    }
    for (int i = idx; i < 2 * G4; i += stride) {
        int dir = i / G4, r = i - dir * G4;
        g_bias[dir][r] = (dir ? b_b : b_f)[(r & 3) * HID + (r >> 2)];
    }
    for (int i = idx; i < 2 * 2 * BS * KTOT; i += stride) {
        int buf = i / (2 * BS * KTOT);
        int rem = i - buf * (2 * BS * KTOT);
        int dir = rem / (BS * KTOT);
        int rem2 = rem - dir * (BS * KTOT);
        int row = rem2 / KTOT, k = rem2 - row * KTOT;
        float v = (buf == 0 && k < LATENT) ? dec[row * LATENT + k] : 0.f;
        __nv_bfloat16 hi = __float2bfloat16_rn(v);
        __nv_bfloat16 lo = __float2bfloat16_rn(v - __bfloat162float(hi));
        g_Ahi[buf][dir][row][k] = hi;
        g_Alo[buf][dir][row][k] = lo;
    }
    for (int i = idx; i < 2 * 2 * BS * HID; i += stride) ((float*)g_h)[i] = 0.f;
    for (int i = idx; i < 2 * BS * HID; i += stride)     ((float*)g_c)[i] = 0.f;
}

// ---------------------------------------------------------------------------
// persistent kernel: 128 blocks x 256 threads, one launch for all T steps.
// phase A: block = (dir, 64 gate-cols). z via bf16 3-split mma.sync HMMA,
//          cp.async 3-stage smem pipeline, fp32 accum, LSTM cell in epilogue.
// phase B: head (x_next GEMM + fc1), FFMA2.
// ---------------------------------------------------------------------------
__global__ void __launch_bounds__(NTHR, 1) lstm_persist(
        int T, float* __restrict__ out,
        const float* __restrict__ W_out, const float* __restrict__ b_out,
        const float* __restrict__ W_fc1, const float* __restrict__ b_fc1) {

    extern __shared__ __align__(16) unsigned char dsm[];
    const u32 smem_base = smem_u32(dsm);

    const int tid = threadIdx.x;
    const int bid = blockIdx.x;
    const int wid = tid >> 5;
    const int lane = tid & 31;

    const int dir = bid >> 6;
    const int colbase = (bid & 63) << 6;

    // warp tile mapping: 4 warps along M (32 rows), 2 along N (32 cols)
    const int wm = wid & 3;
    const int wn = wid >> 2;
    const int R0 = wm * 32;
    const int C0 = wn * 32;

    // ldmatrix per-lane constants
    const int arow = lane & 15;                          // A: m16 row within tile
    const u32 khA = (u32)(lane >> 4) * 16;               // A: k-half byte offset
    const int brow = (lane & 7) + ((lane >> 4) & 1) * 8; // B: n row within n16 pair
    const u32 khB = (u32)((lane >> 3) & 1) * 16;         // B: k-half byte offset
    const u32 swA = (u32)(arow & 7) << 4;
    const u32 swB = (u32)(brow & 7) << 4;
    // stage-relative byte offsets of the ldmatrix base rows
    const u32 aRowOff0 = (u32)(R0 + arow) * 128;
    const u32 aRowOff1 = (u32)(R0 + 16 + arow) * 128;
    const u32 bRowOff0 = OFF_WH + (u32)(C0 + brow) * 128;
    const u32 bRowOff1 = OFF_WH + (u32)(C0 + 16 + brow) * 128;

    // cp.async per-thread source/dest precompute
    u32 cpdst[6];   // stage-relative swizzled offsets (4 A rows + 2 W rows)
    int cprowA[4], cprowW[2], cpq[6];
#pragma unroll
    for (int i = 0; i < 4; i++) {
        int p = tid + i * NTHR, row = p >> 3, q = p & 7;
        cprowA[i] = row; cpq[i] = q;
        cpdst[i] = SW128((u32)(row * 128 + q * 16));
    }
#pragma unroll
    for (int i = 0; i < 2; i++) {
        int p = tid + i * NTHR, row = p >> 3, q = p & 7;
        cprowW[i] = row; cpq[4 + i] = q;
        cpdst[4 + i] = SW128((u32)(row * 128 + q * 16));
    }

    // head mapping
    const int bt = bid >> 3;   // 16 row-tiles of 8
    const int lt = bid & 7;    // 8 latent col-tiles of 64
    float (*s_hb)[HID] = (float (*)[HID])dsm;

    u64 nbar = 0;

    for (int t = 0; t < T; t++) {
        const int cur = t & 1;
        const int nxt = cur ^ 1;
        const __nv_bfloat16* __restrict__ Ah = &g_Ahi[cur][dir][0][0];
        const __nv_bfloat16* __restrict__ Al = &g_Alo[cur][dir][0][0];
        const __nv_bfloat16* __restrict__ Wh = &g_Whi[dir][colbase][0];
        const __nv_bfloat16* __restrict__ Wl = &g_Wlo[dir][colbase][0];

        // ================= phase A: bf16-split HMMA, cp.async pipeline =====
        float acc[2][4][4];
#pragma unroll
        for (int mt = 0; mt < 2; mt++)
#pragma unroll
            for (int nt = 0; nt < 4; nt++)
#pragma unroll
                for (int i = 0; i < 4; i++) acc[mt][nt][i] = 0.f;

        // issue chunk 0 into stage 0
        {
            const u32 sb = smem_base;
#pragma unroll
            for (int i = 0; i < 4; i++) {
                const char* s = (const char*)(Ah + (size_t)cprowA[i] * KTOT) + cpq[i] * 16;
                const char* s2 = (const char*)(Al + (size_t)cprowA[i] * KTOT) + cpq[i] * 16;
                CP16(sb + cpdst[i], s);
                CP16(sb + OFF_AL + cpdst[i], s2);
            }
#pragma unroll
            for (int i = 0; i < 2; i++) {
                const char* s = (const char*)(Wh + (size_t)cprowW[i] * KTOT) + cpq[4 + i] * 16;
                const char* s2 = (const char*)(Wl + (size_t)cprowW[i] * KTOT) + cpq[4 + i] * 16;
                CP16(sb + OFF_WH + cpdst[4 + i], s);
                CP16(sb + OFF_WL + cpdst[4 + i], s2);
            }
            CP_COMMIT();
        }

        int stage = 0;
#pragma unroll 1
        for (int c = 0; c < NCHUNK; c++) {
            if (c + 1 < NCHUNK) {
                // issue chunk c+1 into next stage
                const int nstage = (stage == 2) ? 0 : stage + 1;
                const u32 sb = smem_base + (u32)nstage * STG;
                const size_t c64 = (size_t)(c + 1) * CHK;
#pragma unroll
                for (int i = 0; i < 4; i++) {
                    const char* s = (const char*)(Ah + (size_t)cprowA[i] * KTOT + c64) + cpq[i] * 16;
                    const char* s2 = (const char*)(Al + (size_t)cprowA[i] * KTOT + c64) + cpq[i] * 16;
                    CP16(sb + cpdst[i], s);
                    CP16(sb + OFF_AL + cpdst[i], s2);
                }
#pragma unroll
                for (int i = 0; i < 2; i++) {
                    const char* s = (const char*)(Wh + (size_t)cprowW[i] * KTOT + c64) + cpq[4 + i] * 16;
                    const char* s2 = (const char*)(Wl + (size_t)cprowW[i] * KTOT + c64) + cpq[4 + i] * 16;
                    CP16(sb + OFF_WH + cpdst[4 + i], s);
                    CP16(sb + OFF_WL + cpdst[4 + i], s2);
                }
                CP_COMMIT();
                CP_WAIT(1);          // chunk c complete (chunk c+1 may be in flight)
            } else {
                CP_WAIT(0);          // last chunk complete
            }
            __syncthreads();         // chunk c visible to all warps; also protects
                                     // stage reuse (ring period 3, see analysis)

            const u32 sb = smem_base + (u32)stage * STG;
            const u32 a0 = sb + aRowOff0, a1 = sb + aRowOff1;
            const u32 b0 = sb + bRowOff0, b1 = sb + bRowOff1;

#pragma unroll
            for (int kk = 0; kk < 4; kk++) {
                const u32 xA = ((u32)(kk * 32) + khA) ^ swA;
                const u32 xB = ((u32)(kk * 32) + khB) ^ swB;
                u32 ah[2][4], al[2][4], bh[2][4], bl[2][4];
                LDSM4(ah[0], a0 + xA);
                LDSM4(ah[1], a1 + xA);
                LDSM4(al[0], a0 + OFF_AL + xA);
                LDSM4(al[1], a1 + OFF_AL + xA);
                LDSM4(bh[0], b0 + xB);
                LDSM4(bh[1], b1 + xB);
                LDSM4(bl[0], b0 + (OFF_WL - OFF_WH) + xB);
                LDSM4(bl[1], b1 + (OFF_WL - OFF_WH) + xB);
#pragma unroll
                for (int mt = 0; mt < 2; mt++)
#pragma unroll
                    for (int np = 0; np < 2; np++)
#pragma unroll
                        for (int hf = 0; hf < 2; hf++) {
                            const int nt = np * 2 + hf;
                            MMA16816(acc[mt][nt], ah[mt], bh[np][2 * hf], bh[np][2 * hf + 1]);
                            MMA16816(acc[mt][nt], ah[mt], bl[np][2 * hf], bl[np][2 * hf + 1]);
                            MMA16816(acc[mt][nt], al[mt], bh[np][2 * hf], bh[np][2 * hf + 1]);
                        }
            }
            stage = (stage == 2) ? 0 : stage + 1;
        }

        // -------- epilogue: pair-exchange quads, LSTM cell, write h --------
#pragma unroll
        for (int mt = 0; mt < 2; mt++)
#pragma unroll
            for (int nt = 0; nt < 4; nt++) {
                float d0 = acc[mt][nt][0], d1 = acc[mt][nt][1];
                float d2 = acc[mt][nt][2], d3 = acc[mt][nt][3];
                float p0 = __shfl_xor_sync(0xffffffffu, d0, 1);
                float p1 = __shfl_xor_sync(0xffffffffu, d1, 1);
                float p2 = __shfl_xor_sync(0xffffffffu, d2, 1);
                float p3 = __shfl_xor_sync(0xffffffffu, d3, 1);
                if (!(lane & 1)) {
                    const int q = (lane >> 1) & 1;
                    const int col4 = colbase + C0 + nt * 8 + q * 4;
                    const int jp = col4 >> 2;
                    const float4 b4 = *(const float4*)&g_bias[dir][col4];
                    const int r0 = R0 + mt * 16 + (lane >> 2);
#pragma unroll
                    for (int rr = 0; rr < 2; rr++) {
                        const int row = r0 + rr * 8;
                        float zi = (rr ? d2 : d0) + b4.x;
                        float zf = (rr ? d3 : d1) + b4.y;
                        float zg = (rr ? p2 : p0) + b4.z;
                        float zo = (rr ? p3 : p1) + b4.w;
                        float si = 1.f / (1.f + expf(-zi));
                        float sf = 1.f / (1.f + expf(-zf));
                        float so = 1.f / (1.f + expf(-zo));
                        float c2 = sf * g_c[dir][row][jp] + si * tanhf(zg);
                        g_c[dir][row][jp] = c2;
                        float hv = so * tanhf(c2);
                        g_h[nxt][dir][row][jp] = hv;
                        __nv_bfloat16 hhi = __float2bfloat16_rn(hv);
                        __nv_bfloat16 hlo = __float2bfloat16_rn(hv - __bfloat162float(hhi));
                        g_Ahi[nxt][dir][row][LATENT + jp] = hhi;
                        g_Alo[nxt][dir][row][LATENT + jp] = hlo;
                    }
                }
            }

        nbar++; grid_sync(nbar * NBLK);

        // ================= phase B: head ===================================
        for (int i = tid; i < 8 * HID / 4; i += NTHR) {
            int r = (i * 4) >> 10;
            int k = (i * 4) & (HID - 1);
            *(float4*)&s_hb[r][k] = *(const float4*)&g_h[nxt][1][bt * 8 + r][k];
        }
        __syncthreads();

        // x_next = hb @ W_out^T + b_out, split to bf16 hi/lo for both dirs
        {
            const int l_loc = tid >> 2;
            const int q = tid & 3;
            const int l = lt * 64 + l_loc;
            const u64* __restrict__ wp = (const u64*)(W_out + (size_t)l * HID + q * 256);
            const u64* __restrict__ hp = (const u64*)&s_hb[0][q * 256];
            u64 hacc[8];
#pragma unroll
            for (int r = 0; r < 8; r++) hacc[r] = 0ull;
#pragma unroll 2
            for (int k2 = 0; k2 < 128; k2++) {
                u64 w = wp[k2];
#pragma unroll
                for (int r = 0; r < 8; r++) fma2(hacc[r], w, hp[r * 512 + k2]);
            }
#pragma unroll
            for (int r = 0; r < 8; r++) {
                float lo, hi; unpack2(hacc[r], lo, hi);
                float s = lo + hi;
                s += __shfl_xor_sync(0xffffffffu, s, 1);
                s += __shfl_xor_sync(0xffffffffu, s, 2);
                if (q == 0) {
                    float xv = s + b_out[l];
                    int row = bt * 8 + r;
                    __nv_bfloat16 xh = __float2bfloat16_rn(xv);
                    __nv_bfloat16 xl = __float2bfloat16_rn(xv - __bfloat162float(xh));
                    g_Ahi[nxt][0][row][l] = xh;
                    g_Ahi[nxt][1][row][l] = xh;
                    g_Alo[nxt][0][row][l] = xl;
                    g_Alo[nxt][1][row][l] = xl;
                }
            }
        }

        // out[b, t] = relu(concat(hf,hb)) . W_fc1 + b_fc1   (lt==0 blocks)
        if (lt == 0) {
            const int r = tid >> 5, ln = tid & 31;
            const int b = bt * 8 + r;
            const float* __restrict__ hf = &g_h[nxt][0][b][0];
            float facc = 0.f;
            for (int k = ln * 4; k < HID; k += 128) {
                float4 f   = *(const float4*)&hf[k];
                float4 wf  = *(const float4*)&W_fc1[k];
                float4 hb4 = *(const float4*)&s_hb[r][k];
                float4 wb  = *(const float4*)&W_fc1[HID + k];
                facc += fmaxf(f.x, 0.f) * wf.x + fmaxf(f.y, 0.f) * wf.y
                      + fmaxf(f.z, 0.f) * wf.z + fmaxf(f.w, 0.f) * wf.w
                      + fmaxf(hb4.x, 0.f) * wb.x + fmaxf(hb4.y, 0.f) * wb.y
                      + fmaxf(hb4.z, 0.f) * wb.z + fmaxf(hb4.w, 0.f) * wb.w;
            }
#pragma unroll
            for (int off = 16; off; off >>= 1)
                facc += __shfl_xor_sync(0xffffffffu, facc, off);
            if (ln == 0) out[(size_t)b * T + t] = facc + b_fc1[0];
        }

        nbar++; grid_sync(nbar * NBLK);
    }
}

// ---------------------------------------------------------------------------
extern "C" void kernel_launch(void* const* d_in, const int* in_sizes, int n_in,
                              void* d_out, int out_size) {
    const float* dec   = (const float*)d_in[0];
    // d_in[1] = lengths (T derives from out_size)
    const float* Wih_f = (const float*)d_in[2];
    const float* Whh_f = (const float*)d_in[3];
    const float* b_f   = (const float*)d_in[4];
    const float* Wih_b = (const float*)d_in[5];
    const float* Whh_b = (const float*)d_in[6];
    const float* b_b   = (const float*)d_in[7];
    const float* W_out = (const float*)d_in[8];
    const float* b_out = (const float*)d_in[9];
    const float* W_fc1 = (const float*)d_in[10];
    const float* b_fc1 = (const float*)d_in[11];
    float* out = (float*)d_out;

    const int T = out_size / BS;

    static int attr_done = 0;
    if (!attr_done) {
        cudaFuncSetAttribute(lstm_persist, cudaFuncAttributeMaxDynamicSharedMemorySize, DYN_SMEM);
        attr_done = 1;
    }

    prep_kernel<<<1024, 256>>>(Wih_f, Whh_f, b_f, Wih_b, Whh_b, b_b, dec);
    if (T > 0) {
        lstm_persist<<<NBLK, NTHR, DYN_SMEM>>>(T, out, W_out, b_out, W_fc1, b_fc1);
    }
}